// round 7
// baseline (speedup 1.0000x reference)
#include <cuda_runtime.h>

#define NMAX 50048
#define EMAX 860032
#define SLOTS 96

typedef unsigned long long u64;

// ---------------- scratch ----------------------------------------------------
__device__ float g_h1t[NMAX * 128];    // layer-1 linear out, transposed [node][ch][head]
__device__ float g_hmid[NMAX * 128];   // relu(agg1+b1), standard [node][head*32+ch]
__device__ float g_h2t[NMAX * 64];     // layer-2 linear out, transposed [node][ch%32][ch/32]
__device__ float g_as1[NMAX * 4];
__device__ float g_ad1[NMAX * 4];
__device__ float g_as2[NMAX];
__device__ float g_ad2[NMAX];
__device__ int   g_cur[NMAX];
__device__ int   g_ell[NMAX * SLOTS];

// ---------------- f32x2 helpers ----------------------------------------------
__device__ __forceinline__ u64 ffma2(u64 a, u64 b, u64 c) {
    u64 d;
    asm("fma.rn.f32x2 %0, %1, %2, %3;" : "=l"(d) : "l"(a), "l"(b), "l"(c));
    return d;
}
__device__ __forceinline__ u64 splat2(float x) {
    u64 d;
    asm("mov.b64 %0, {%1, %1};" : "=l"(d) : "f"(x));
    return d;
}
__device__ __forceinline__ void unpack2(u64 v, float& x, float& y) {
    asm("mov.b64 {%0, %1}, %2;" : "=f"(x), "=f"(y) : "l"(v));
}

__global__ void zero_cur_kernel(int n) {
    int i = blockIdx.x * blockDim.x + threadIdx.x;
    if (i < n) g_cur[i] = 0;
}

// ---------------- fused GEMM1 (+att1 epilogue) + ELL fill --------------------
// gemm blocks: C[M,128] = A[M,128] @ W1[128,128], BM=64, BN=128, BK=16, 4x8/thread
// fill blocks: scatter edges into ELL table
__global__ __launch_bounds__(256, 3) void gemm1_fill_kernel(
    const float* __restrict__ A, const float* __restrict__ B,
    const float* __restrict__ attS, const float* __restrict__ attD,
    const int* __restrict__ esrc, const int* __restrict__ edst,
    int M, int E, int gemmBlocks)
{
    __shared__ float As[16][64];    // 4KB
    __shared__ float Bs[16][128];   // 8KB
    int tid = threadIdx.x;

    if (blockIdx.x >= gemmBlocks) {
        int base = ((blockIdx.x - gemmBlocks) * 256 + tid) * 4;
        if (base + 3 < E) {
            int4 s = *(const int4*)(esrc + base);
            int4 d = *(const int4*)(edst + base);
            int p;
            p = atomicAdd(&g_cur[d.x], 1); if (p < SLOTS) g_ell[d.x * SLOTS + p] = s.x;
            p = atomicAdd(&g_cur[d.y], 1); if (p < SLOTS) g_ell[d.y * SLOTS + p] = s.y;
            p = atomicAdd(&g_cur[d.z], 1); if (p < SLOTS) g_ell[d.z * SLOTS + p] = s.z;
            p = atomicAdd(&g_cur[d.w], 1); if (p < SLOTS) g_ell[d.w * SLOTS + p] = s.w;
        } else {
            for (int e = base; e < E; e++) {
                int dd = edst[e];
                int p = atomicAdd(&g_cur[dd], 1);
                if (p < SLOTS) g_ell[dd * SLOTS + p] = esrc[e];
            }
        }
        return;
    }

    int tx = tid & 15, ty = tid >> 4;     // 16 col-groups x 16 row-groups
    int rowBase = blockIdx.x * 64;
    u64 acc[4][4];
    #pragma unroll
    for (int i = 0; i < 4; i++)
        #pragma unroll
        for (int j = 0; j < 4; j++) acc[i][j] = 0ull;

    for (int k0 = 0; k0 < 128; k0 += 16) {
        {   // A tile 64x16 = 256 float4, one per thread
            int r = tid >> 2, kq = (tid & 3) * 4;
            int grow = rowBase + r;
            float4 v = make_float4(0.f, 0.f, 0.f, 0.f);
            if (grow < M) v = *(const float4*)(A + grow * 128 + k0 + kq);
            As[kq + 0][r] = v.x; As[kq + 1][r] = v.y;
            As[kq + 2][r] = v.z; As[kq + 3][r] = v.w;
        }
        {   // B tile 16x128 = 512 float4, two per thread
            int rk = tid >> 5, c = (tid & 31) * 4;
            *(float4*)&Bs[rk][c]     = *(const float4*)(B + (k0 + rk) * 128 + c);
            *(float4*)&Bs[rk + 8][c] = *(const float4*)(B + (k0 + rk + 8) * 128 + c);
        }
        __syncthreads();
        #pragma unroll
        for (int kk = 0; kk < 16; kk++) {
            float4 a0 = *(const float4*)&As[kk][ty * 4];
            const u64* bp = (const u64*)&Bs[kk][tx * 8];
            u64 b0 = bp[0], b1 = bp[1], b2 = bp[2], b3 = bp[3];
            float ar[4] = {a0.x, a0.y, a0.z, a0.w};
            #pragma unroll
            for (int i = 0; i < 4; i++) {
                u64 aa = splat2(ar[i]);
                acc[i][0] = ffma2(aa, b0, acc[i][0]);
                acc[i][1] = ffma2(aa, b1, acc[i][1]);
                acc[i][2] = ffma2(aa, b2, acc[i][2]);
                acc[i][3] = ffma2(aa, b3, acc[i][3]);
            }
        }
        __syncthreads();
    }

    // epilogue: transposed store + fused att reductions
    int head = tx >> 2, chb = (tx & 3) * 8;
    #pragma unroll
    for (int i = 0; i < 4; i++) {
        int r = rowBase + ty * 4 + i;
        float f[8];
        unpack2(acc[i][0], f[0], f[1]); unpack2(acc[i][1], f[2], f[3]);
        unpack2(acc[i][2], f[4], f[5]); unpack2(acc[i][3], f[6], f[7]);
        float sp = 0.f, dp = 0.f;
        #pragma unroll
        for (int j = 0; j < 8; j++) {
            sp = fmaf(f[j], attS[head * 32 + chb + j], sp);
            dp = fmaf(f[j], attD[head * 32 + chb + j], dp);
        }
        sp += __shfl_xor_sync(0xffffffffu, sp, 1); sp += __shfl_xor_sync(0xffffffffu, sp, 2);
        dp += __shfl_xor_sync(0xffffffffu, dp, 1); dp += __shfl_xor_sync(0xffffffffu, dp, 2);
        if (r < M) {
            #pragma unroll
            for (int j = 0; j < 8; j++)
                g_h1t[r * 128 + (chb + j) * 4 + head] = f[j];
            if ((tx & 3) == 0) {
                g_as1[r * 4 + head] = sp;
                g_ad1[r * 4 + head] = dp;
            }
        }
    }
}

// ---------------- GEMM2 (+att2 epilogue) -------------------------------------
// C[M,64] = hmid[M,128] @ W2[128,64], BM=128, BN=64, BK=16, 4x8/thread
__global__ __launch_bounds__(256, 3) void gemm2_kernel(
    const float* __restrict__ A, const float* __restrict__ B,
    const float* __restrict__ attS, const float* __restrict__ attD, int M)
{
    __shared__ float As[16][128];   // 8KB
    __shared__ float Bs[16][64];    // 4KB
    int tid = threadIdx.x;
    int tx = tid & 7, ty = tid >> 3;    // 8 col-groups x 32 row-groups
    int rowBase = blockIdx.x * 128;
    u64 acc[4][4];
    #pragma unroll
    for (int i = 0; i < 4; i++)
        #pragma unroll
        for (int j = 0; j < 4; j++) acc[i][j] = 0ull;

    for (int k0 = 0; k0 < 128; k0 += 16) {
        {   // A tile 128x16 = 512 float4, two per thread
            int r = tid >> 1, kq = (tid & 1) * 8;
            int grow = rowBase + r;
            float4 v0 = make_float4(0.f, 0.f, 0.f, 0.f), v1 = v0;
            if (grow < M) {
                v0 = *(const float4*)(A + grow * 128 + k0 + kq);
                v1 = *(const float4*)(A + grow * 128 + k0 + kq + 4);
            }
            As[kq + 0][r] = v0.x; As[kq + 1][r] = v0.y;
            As[kq + 2][r] = v0.z; As[kq + 3][r] = v0.w;
            As[kq + 4][r] = v1.x; As[kq + 5][r] = v1.y;
            As[kq + 6][r] = v1.z; As[kq + 7][r] = v1.w;
        }
        {   // B tile 16x64 = 256 float4, one per thread
            int rk = tid >> 4, c = (tid & 15) * 4;
            *(float4*)&Bs[rk][c] = *(const float4*)(B + (k0 + rk) * 64 + c);
        }
        __syncthreads();
        #pragma unroll
        for (int kk = 0; kk < 16; kk++) {
            float4 a0 = *(const float4*)&As[kk][ty * 4];
            const u64* bp = (const u64*)&Bs[kk][tx * 8];
            u64 b0 = bp[0], b1 = bp[1], b2 = bp[2], b3 = bp[3];
            float ar[4] = {a0.x, a0.y, a0.z, a0.w};
            #pragma unroll
            for (int i = 0; i < 4; i++) {
                u64 aa = splat2(ar[i]);
                acc[i][0] = ffma2(aa, b0, acc[i][0]);
                acc[i][1] = ffma2(aa, b1, acc[i][1]);
                acc[i][2] = ffma2(aa, b2, acc[i][2]);
                acc[i][3] = ffma2(aa, b3, acc[i][3]);
            }
        }
        __syncthreads();
    }

    #pragma unroll
    for (int i = 0; i < 4; i++) {
        int r = rowBase + ty * 4 + i;
        float f[8];
        unpack2(acc[i][0], f[0], f[1]); unpack2(acc[i][1], f[2], f[3]);
        unpack2(acc[i][2], f[4], f[5]); unpack2(acc[i][3], f[6], f[7]);
        float sp = 0.f, dp = 0.f;
        #pragma unroll
        for (int j = 0; j < 8; j++) {
            sp = fmaf(f[j], attS[tx * 8 + j], sp);
            dp = fmaf(f[j], attD[tx * 8 + j], dp);
        }
        // reduce over tx (lane bits 0-2)
        sp += __shfl_xor_sync(0xffffffffu, sp, 1);
        sp += __shfl_xor_sync(0xffffffffu, sp, 2);
        sp += __shfl_xor_sync(0xffffffffu, sp, 4);
        dp += __shfl_xor_sync(0xffffffffu, dp, 1);
        dp += __shfl_xor_sync(0xffffffffu, dp, 2);
        dp += __shfl_xor_sync(0xffffffffu, dp, 4);
        if (r < M) {
            #pragma unroll
            for (int j = 0; j < 8; j++) {
                int c = tx * 8 + j;
                g_h2t[r * 64 + (c & 31) * 2 + (c >> 5)] = f[j];
            }
            if (tx == 0) { g_as2[r] = sp; g_ad2[r] = dp; }
        }
    }
}

// ---------------- aggregation: exp distributed across lanes ------------------
__global__ __launch_bounds__(256) void agg1_kernel(const float* __restrict__ b1, int n) {
    __shared__ float4 wbuf[8][32];
    __shared__ int    sbuf[8][32];
    int w = threadIdx.x >> 5, lane = threadIdx.x & 31;
    int node = blockIdx.x * 8 + w;
    if (node >= n) return;
    float4 ad = *(const float4*)(g_ad1 + node * 4);
    int deg = g_cur[node]; if (deg > SLOTS) deg = SLOTS;
    const int* ep = g_ell + node * SLOTS;
    float s0 = 0.f, s1 = 0.f, s2 = 0.f, s3 = 0.f;
    float a0 = 0.f, a1 = 0.f, a2 = 0.f, a3 = 0.f;

    for (int base = 0; base < deg; base += 32) {
        int i = base + lane;
        float4 wv = make_float4(0.f, 0.f, 0.f, 0.f);
        int src = 0;
        if (i < deg) {
            src = ep[i];
            float4 asv = *(const float4*)(g_as1 + src * 4);
            float e;
            e = asv.x + ad.x; e = e > 0.f ? e : 0.2f * e; wv.x = __expf(fminf(e, 80.f));
            e = asv.y + ad.y; e = e > 0.f ? e : 0.2f * e; wv.y = __expf(fminf(e, 80.f));
            e = asv.z + ad.z; e = e > 0.f ? e : 0.2f * e; wv.z = __expf(fminf(e, 80.f));
            e = asv.w + ad.w; e = e > 0.f ? e : 0.2f * e; wv.w = __expf(fminf(e, 80.f));
        }
        wbuf[w][lane] = wv;
        sbuf[w][lane] = src;
        __syncwarp();
        int cnt = deg - base; if (cnt > 32) cnt = 32;
        if (cnt == 32) {
            #pragma unroll 4
            for (int j = 0; j < 32; j++) {
                float4 q = wbuf[w][j];
                int sj = sbuf[w][j];
                float4 v = *(const float4*)(g_h1t + sj * 128 + lane * 4);
                s0 += q.x; a0 = fmaf(q.x, v.x, a0);
                s1 += q.y; a1 = fmaf(q.y, v.y, a1);
                s2 += q.z; a2 = fmaf(q.z, v.z, a2);
                s3 += q.w; a3 = fmaf(q.w, v.w, a3);
            }
        } else {
            for (int j = 0; j < cnt; j++) {
                float4 q = wbuf[w][j];
                int sj = sbuf[w][j];
                float4 v = *(const float4*)(g_h1t + sj * 128 + lane * 4);
                s0 += q.x; a0 = fmaf(q.x, v.x, a0);
                s1 += q.y; a1 = fmaf(q.y, v.y, a1);
                s2 += q.z; a2 = fmaf(q.z, v.z, a2);
                s3 += q.w; a3 = fmaf(q.w, v.w, a3);
            }
        }
        __syncwarp();
    }
    float o;
    o = a0 / s0 + b1[lane];       g_hmid[node * 128 + lane]      = fmaxf(o, 0.f);
    o = a1 / s1 + b1[32 + lane];  g_hmid[node * 128 + 32 + lane] = fmaxf(o, 0.f);
    o = a2 / s2 + b1[64 + lane];  g_hmid[node * 128 + 64 + lane] = fmaxf(o, 0.f);
    o = a3 / s3 + b1[96 + lane];  g_hmid[node * 128 + 96 + lane] = fmaxf(o, 0.f);
}

__global__ __launch_bounds__(256) void agg2_kernel(const float* __restrict__ b2,
                                                   float* __restrict__ out, int n) {
    __shared__ float wbuf[8][32];
    __shared__ int   sbuf[8][32];
    int w = threadIdx.x >> 5, lane = threadIdx.x & 31;
    int node = blockIdx.x * 8 + w;
    if (node >= n) return;
    float ad = g_ad2[node];
    int deg = g_cur[node]; if (deg > SLOTS) deg = SLOTS;
    const int* ep = g_ell + node * SLOTS;
    float s = 0.f, a0 = 0.f, a1 = 0.f;

    for (int base = 0; base < deg; base += 32) {
        int i = base + lane;
        float wv = 0.f; int src = 0;
        if (i < deg) {
            src = ep[i];
            float e = g_as2[src] + ad;
            e = e > 0.f ? e : 0.2f * e;
            wv = __expf(fminf(e, 80.f));
        }
        wbuf[w][lane] = wv;
        sbuf[w][lane] = src;
        __syncwarp();
        int cnt = deg - base; if (cnt > 32) cnt = 32;
        if (cnt == 32) {
            #pragma unroll 4
            for (int j = 0; j < 32; j++) {
                float q = wbuf[w][j];
                int sj = sbuf[w][j];
                float2 v = *(const float2*)(g_h2t + sj * 64 + lane * 2);
                s += q; a0 = fmaf(q, v.x, a0); a1 = fmaf(q, v.y, a1);
            }
        } else {
            for (int j = 0; j < cnt; j++) {
                float q = wbuf[w][j];
                int sj = sbuf[w][j];
                float2 v = *(const float2*)(g_h2t + sj * 64 + lane * 2);
                s += q; a0 = fmaf(q, v.x, a0); a1 = fmaf(q, v.y, a1);
            }
        }
        __syncwarp();
    }
    float r = 1.f / s;
    out[node * 64 + lane]      = a0 * r + b2[lane];
    out[node * 64 + 32 + lane] = a1 * r + b2[32 + lane];
}

// ---------------- launch -----------------------------------------------------
extern "C" void kernel_launch(void* const* d_in, const int* in_sizes, int n_in,
                              void* d_out, int out_size) {
    const float* x    = (const float*)d_in[0];
    const int*   esrc = (const int*)d_in[1];
    const int*   edst = (const int*)d_in[2];
    const float* W1   = (const float*)d_in[3];
    const float* as1w = (const float*)d_in[4];
    const float* ad1w = (const float*)d_in[5];
    const float* b1   = (const float*)d_in[6];
    const float* W2   = (const float*)d_in[7];
    const float* as2w = (const float*)d_in[8];
    const float* ad2w = (const float*)d_in[9];
    const float* b2   = (const float*)d_in[10];
    float* out = (float*)d_out;

    int n = in_sizes[0] / 128;
    int E = in_sizes[1];

    void* p;
    float* hmid;
    cudaGetSymbolAddress(&p, g_hmid); hmid = (float*)p;

    zero_cur_kernel<<<(n + 255) / 256, 256>>>(n);

    int gemmBlocks = (n + 63) / 64;
    int fillBlocks = (E + 1023) / 1024;
    gemm1_fill_kernel<<<gemmBlocks + fillBlocks, 256>>>(x, W1, as1w, ad1w,
                                                        esrc, edst, n, E, gemmBlocks);
    int aggBlocks = (n + 7) / 8;
    agg1_kernel<<<aggBlocks, 256>>>(b1, n);
    gemm2_kernel<<<(n + 127) / 128, 256>>>(hmid, W2, as2w, ad2w, n);
    agg2_kernel<<<aggBlocks, 256>>>(b2, out, n);
}

// round 8
// speedup vs baseline: 1.2959x; 1.2959x over previous
#include <cuda_runtime.h>
#include <cuda_fp16.h>

#define NMAX 50048
#define EMAX 860032
#define SLOTS 96

typedef unsigned long long u64;

// ---------------- scratch ----------------------------------------------------
__device__ __half g_h1th[NMAX * 128];  // layer-1 linear out, fp16, [node][ch][head]
__device__ float g_hmid[NMAX * 128];   // relu(agg1+b1), fp32
__device__ float g_h2t[NMAX * 64];     // layer-2 linear out, [node][ch%32][ch/32]
__device__ float g_as1[NMAX * 4];
__device__ float g_ad1[NMAX * 4];
__device__ float g_as2[NMAX];
__device__ float g_ad2[NMAX];
__device__ int   g_cur[NMAX];
__device__ int   g_ell[NMAX * SLOTS];

// ---------------- helpers -----------------------------------------------------
__device__ __forceinline__ u64 ffma2(u64 a, u64 b, u64 c) {
    u64 d;
    asm("fma.rn.f32x2 %0, %1, %2, %3;" : "=l"(d) : "l"(a), "l"(b), "l"(c));
    return d;
}
__device__ __forceinline__ u64 splat2(float x) {
    u64 d;
    asm("mov.b64 %0, {%1, %1};" : "=l"(d) : "f"(x));
    return d;
}
__device__ __forceinline__ void unpack2(u64 v, float& x, float& y) {
    asm("mov.b64 {%0, %1}, %2;" : "=f"(x), "=f"(y) : "l"(v));
}
__device__ __forceinline__ void cpasync16(void* dst, const void* src) {
    unsigned int d = (unsigned int)__cvta_generic_to_shared(dst);
    asm volatile("cp.async.cg.shared.global [%0], [%1], 16;" :: "r"(d), "l"(src));
}
#define CP_COMMIT() asm volatile("cp.async.commit_group;")
#define CP_WAIT0()  asm volatile("cp.async.wait_group 0;")

__global__ void zero_cur_kernel(int n) {
    int i = blockIdx.x * blockDim.x + threadIdx.x;
    if (i < n) g_cur[i] = 0;
}

// ---------------- fused GEMM1 (+att1 epilogue) + ELL fill --------------------
// gemm blocks: C[M,128] = A[M,128] @ W1[128,128], BM=128, BN=128, BK=16, 8x8/thread
// double-buffered: cp.async for B, reg-prefetch for A
__global__ __launch_bounds__(256) void gemm1_fill_kernel(
    const float* __restrict__ A, const float* __restrict__ B,
    const float* __restrict__ attS, const float* __restrict__ attD,
    const int* __restrict__ esrc, const int* __restrict__ edst,
    int M, int E, int gemmBlocks)
{
    __shared__ float As[2][16][128];   // 16KB
    __shared__ float Bs[2][16][128];   // 16KB
    int tid = threadIdx.x;

    if (blockIdx.x >= gemmBlocks) {
        int base = ((blockIdx.x - gemmBlocks) * 256 + tid) * 4;
        if (base + 3 < E) {
            int4 s = *(const int4*)(esrc + base);
            int4 d = *(const int4*)(edst + base);
            int p;
            p = atomicAdd(&g_cur[d.x], 1); if (p < SLOTS) g_ell[d.x * SLOTS + p] = s.x;
            p = atomicAdd(&g_cur[d.y], 1); if (p < SLOTS) g_ell[d.y * SLOTS + p] = s.y;
            p = atomicAdd(&g_cur[d.z], 1); if (p < SLOTS) g_ell[d.z * SLOTS + p] = s.z;
            p = atomicAdd(&g_cur[d.w], 1); if (p < SLOTS) g_ell[d.w * SLOTS + p] = s.w;
        } else {
            for (int e = base; e < E; e++) {
                int dd = edst[e];
                int p = atomicAdd(&g_cur[dd], 1);
                if (p < SLOTS) g_ell[dd * SLOTS + p] = esrc[e];
            }
        }
        return;
    }

    int tx = tid & 15, ty = tid >> 4;
    int rowBase = blockIdx.x * 128;
    int ar = tid >> 1, akq = (tid & 1) * 8;      // A loader coords
    int agrow = rowBase + ar;
    u64 acc[8][4];
    #pragma unroll
    for (int i = 0; i < 8; i++)
        #pragma unroll
        for (int j = 0; j < 4; j++) acc[i][j] = 0ull;

    // prologue: tile 0
    {
        float4 v0 = make_float4(0.f,0.f,0.f,0.f), v1 = v0;
        if (agrow < M) {
            v0 = *(const float4*)(A + agrow * 128 + akq);
            v1 = *(const float4*)(A + agrow * 128 + akq + 4);
        }
        As[0][akq + 0][ar] = v0.x; As[0][akq + 1][ar] = v0.y;
        As[0][akq + 2][ar] = v0.z; As[0][akq + 3][ar] = v0.w;
        As[0][akq + 4][ar] = v1.x; As[0][akq + 5][ar] = v1.y;
        As[0][akq + 6][ar] = v1.z; As[0][akq + 7][ar] = v1.w;
        #pragma unroll
        for (int c = 0; c < 2; c++) {
            int chunk = tid + c * 256;           // 512 chunks of 16B
            int rk = chunk >> 5, off = (chunk & 31) * 4;
            cpasync16(&Bs[0][rk][off], B + rk * 128 + off);
        }
        CP_COMMIT(); CP_WAIT0();
        __syncthreads();
    }

    #pragma unroll
    for (int t = 0; t < 8; t++) {
        int p = t & 1;
        float4 v0, v1;
        if (t < 7) {
            int k0n = (t + 1) * 16;
            v0 = make_float4(0.f,0.f,0.f,0.f); v1 = v0;
            if (agrow < M) {
                v0 = *(const float4*)(A + agrow * 128 + k0n + akq);
                v1 = *(const float4*)(A + agrow * 128 + k0n + akq + 4);
            }
            #pragma unroll
            for (int c = 0; c < 2; c++) {
                int chunk = tid + c * 256;
                int rk = chunk >> 5, off = (chunk & 31) * 4;
                cpasync16(&Bs[1 - p][rk][off], B + (k0n + rk) * 128 + off);
            }
            CP_COMMIT();
        }
        #pragma unroll
        for (int kk = 0; kk < 16; kk++) {
            float4 a0 = *(const float4*)&As[p][kk][ty * 8];
            float4 a1 = *(const float4*)&As[p][kk][ty * 8 + 4];
            const u64* bp = (const u64*)&Bs[p][kk][tx * 8];
            u64 b0 = bp[0], b1 = bp[1], b2 = bp[2], b3 = bp[3];
            float arv[8] = {a0.x, a0.y, a0.z, a0.w, a1.x, a1.y, a1.z, a1.w};
            #pragma unroll
            for (int i = 0; i < 8; i++) {
                u64 aa = splat2(arv[i]);
                acc[i][0] = ffma2(aa, b0, acc[i][0]);
                acc[i][1] = ffma2(aa, b1, acc[i][1]);
                acc[i][2] = ffma2(aa, b2, acc[i][2]);
                acc[i][3] = ffma2(aa, b3, acc[i][3]);
            }
        }
        if (t < 7) {
            As[1 - p][akq + 0][ar] = v0.x; As[1 - p][akq + 1][ar] = v0.y;
            As[1 - p][akq + 2][ar] = v0.z; As[1 - p][akq + 3][ar] = v0.w;
            As[1 - p][akq + 4][ar] = v1.x; As[1 - p][akq + 5][ar] = v1.y;
            As[1 - p][akq + 6][ar] = v1.z; As[1 - p][akq + 7][ar] = v1.w;
            CP_WAIT0();
            __syncthreads();
        }
    }

    // epilogue: fp16 transposed store + fused att reductions
    int head = tx >> 2, chb = (tx & 3) * 8;
    #pragma unroll
    for (int i = 0; i < 8; i++) {
        int r = rowBase + ty * 8 + i;
        float f[8];
        unpack2(acc[i][0], f[0], f[1]); unpack2(acc[i][1], f[2], f[3]);
        unpack2(acc[i][2], f[4], f[5]); unpack2(acc[i][3], f[6], f[7]);
        float sp = 0.f, dp = 0.f;
        #pragma unroll
        for (int j = 0; j < 8; j++) {
            sp = fmaf(f[j], attS[head * 32 + chb + j], sp);
            dp = fmaf(f[j], attD[head * 32 + chb + j], dp);
        }
        sp += __shfl_xor_sync(0xffffffffu, sp, 1); sp += __shfl_xor_sync(0xffffffffu, sp, 2);
        dp += __shfl_xor_sync(0xffffffffu, dp, 1); dp += __shfl_xor_sync(0xffffffffu, dp, 2);
        if (r < M) {
            #pragma unroll
            for (int j = 0; j < 8; j++)
                g_h1th[r * 128 + (chb + j) * 4 + head] = __float2half_rn(f[j]);
            if ((tx & 3) == 0) {
                g_as1[r * 4 + head] = sp;
                g_ad1[r * 4 + head] = dp;
            }
        }
    }
}

// ---------------- GEMM2 (+att2 epilogue), pipelined --------------------------
// C[M,64] = hmid[M,128] @ W2[128,64], BM=128, BN=64, BK=16, 8x8/thread, 128 thr
__global__ __launch_bounds__(128) void gemm2_kernel(
    const float* __restrict__ A, const float* __restrict__ B,
    const float* __restrict__ attS, const float* __restrict__ attD, int M)
{
    __shared__ float As[2][16][128];   // 16KB
    __shared__ float Bs[2][16][64];    // 8KB
    int tid = threadIdx.x;
    int tx = tid & 7, ty = tid >> 3;   // 8 col-groups x 16 row-groups
    int rowBase = blockIdx.x * 128;
    int agrow = rowBase + tid;         // one row per thread
    u64 acc[8][4];
    #pragma unroll
    for (int i = 0; i < 8; i++)
        #pragma unroll
        for (int j = 0; j < 4; j++) acc[i][j] = 0ull;

    // prologue
    {
        float4 v[4];
        #pragma unroll
        for (int q = 0; q < 4; q++) v[q] = make_float4(0.f,0.f,0.f,0.f);
        if (agrow < M) {
            #pragma unroll
            for (int q = 0; q < 4; q++) v[q] = *(const float4*)(A + agrow * 128 + q * 4);
        }
        #pragma unroll
        for (int q = 0; q < 4; q++) {
            As[0][q * 4 + 0][tid] = v[q].x; As[0][q * 4 + 1][tid] = v[q].y;
            As[0][q * 4 + 2][tid] = v[q].z; As[0][q * 4 + 3][tid] = v[q].w;
        }
        #pragma unroll
        for (int c = 0; c < 2; c++) {
            int chunk = tid + c * 128;           // 256 chunks
            int rk = chunk >> 4, off = (chunk & 15) * 4;
            cpasync16(&Bs[0][rk][off], B + rk * 64 + off);
        }
        CP_COMMIT(); CP_WAIT0();
        __syncthreads();
    }

    #pragma unroll
    for (int t = 0; t < 8; t++) {
        int p = t & 1;
        float4 v[4];
        if (t < 7) {
            int k0n = (t + 1) * 16;
            #pragma unroll
            for (int q = 0; q < 4; q++) v[q] = make_float4(0.f,0.f,0.f,0.f);
            if (agrow < M) {
                #pragma unroll
                for (int q = 0; q < 4; q++)
                    v[q] = *(const float4*)(A + agrow * 128 + k0n + q * 4);
            }
            #pragma unroll
            for (int c = 0; c < 2; c++) {
                int chunk = tid + c * 128;
                int rk = chunk >> 4, off = (chunk & 15) * 4;
                cpasync16(&Bs[1 - p][rk][off], B + (k0n + rk) * 64 + off);
            }
            CP_COMMIT();
        }
        #pragma unroll
        for (int kk = 0; kk < 16; kk++) {
            float4 a0 = *(const float4*)&As[p][kk][ty * 8];
            float4 a1 = *(const float4*)&As[p][kk][ty * 8 + 4];
            const u64* bp = (const u64*)&Bs[p][kk][tx * 8];
            u64 b0 = bp[0], b1 = bp[1], b2 = bp[2], b3 = bp[3];
            float arv[8] = {a0.x, a0.y, a0.z, a0.w, a1.x, a1.y, a1.z, a1.w};
            #pragma unroll
            for (int i = 0; i < 8; i++) {
                u64 aa = splat2(arv[i]);
                acc[i][0] = ffma2(aa, b0, acc[i][0]);
                acc[i][1] = ffma2(aa, b1, acc[i][1]);
                acc[i][2] = ffma2(aa, b2, acc[i][2]);
                acc[i][3] = ffma2(aa, b3, acc[i][3]);
            }
        }
        if (t < 7) {
            #pragma unroll
            for (int q = 0; q < 4; q++) {
                As[1 - p][q * 4 + 0][tid] = v[q].x; As[1 - p][q * 4 + 1][tid] = v[q].y;
                As[1 - p][q * 4 + 2][tid] = v[q].z; As[1 - p][q * 4 + 3][tid] = v[q].w;
            }
            CP_WAIT0();
            __syncthreads();
        }
    }

    #pragma unroll
    for (int i = 0; i < 8; i++) {
        int r = rowBase + ty * 8 + i;
        float f[8];
        unpack2(acc[i][0], f[0], f[1]); unpack2(acc[i][1], f[2], f[3]);
        unpack2(acc[i][2], f[4], f[5]); unpack2(acc[i][3], f[6], f[7]);
        float sp = 0.f, dp = 0.f;
        #pragma unroll
        for (int j = 0; j < 8; j++) {
            sp = fmaf(f[j], attS[tx * 8 + j], sp);
            dp = fmaf(f[j], attD[tx * 8 + j], dp);
        }
        sp += __shfl_xor_sync(0xffffffffu, sp, 1);
        sp += __shfl_xor_sync(0xffffffffu, sp, 2);
        sp += __shfl_xor_sync(0xffffffffu, sp, 4);
        dp += __shfl_xor_sync(0xffffffffu, dp, 1);
        dp += __shfl_xor_sync(0xffffffffu, dp, 2);
        dp += __shfl_xor_sync(0xffffffffu, dp, 4);
        if (r < M) {
            #pragma unroll
            for (int j = 0; j < 8; j++) {
                int c = tx * 8 + j;
                g_h2t[r * 64 + (c & 31) * 2 + (c >> 5)] = f[j];
            }
            if (tx == 0) { g_as2[r] = sp; g_ad2[r] = dp; }
        }
    }
}

// ---------------- aggregation ------------------------------------------------
__global__ __launch_bounds__(256) void agg1_kernel(const float* __restrict__ b1, int n) {
    __shared__ float4 wbuf[8][32];
    __shared__ int    sbuf[8][32];
    int w = threadIdx.x >> 5, lane = threadIdx.x & 31;
    int node = blockIdx.x * 8 + w;
    if (node >= n) return;
    float4 ad = *(const float4*)(g_ad1 + node * 4);
    int deg = g_cur[node]; if (deg > SLOTS) deg = SLOTS;
    const int* ep = g_ell + node * SLOTS;
    float s0 = 0.f, s1 = 0.f, s2 = 0.f, s3 = 0.f;
    float a0 = 0.f, a1 = 0.f, a2 = 0.f, a3 = 0.f;

    for (int base = 0; base < deg; base += 32) {
        int i = base + lane;
        float4 wv = make_float4(0.f, 0.f, 0.f, 0.f);
        int src = 0;
        if (i < deg) {
            src = ep[i];
            float4 asv = *(const float4*)(g_as1 + src * 4);
            float e;
            e = asv.x + ad.x; e = e > 0.f ? e : 0.2f * e; wv.x = __expf(fminf(e, 80.f));
            e = asv.y + ad.y; e = e > 0.f ? e : 0.2f * e; wv.y = __expf(fminf(e, 80.f));
            e = asv.z + ad.z; e = e > 0.f ? e : 0.2f * e; wv.z = __expf(fminf(e, 80.f));
            e = asv.w + ad.w; e = e > 0.f ? e : 0.2f * e; wv.w = __expf(fminf(e, 80.f));
        }
        wbuf[w][lane] = wv;
        sbuf[w][lane] = src;
        __syncwarp();
        int cnt = deg - base; if (cnt > 32) cnt = 32;
        if (cnt == 32) {
            #pragma unroll 4
            for (int j = 0; j < 32; j++) {
                float4 q = wbuf[w][j];
                int sj = sbuf[w][j];
                const __half2* hp = (const __half2*)(g_h1th + sj * 128 + lane * 4);
                float2 f01 = __half22float2(hp[0]);
                float2 f23 = __half22float2(hp[1]);
                s0 += q.x; a0 = fmaf(q.x, f01.x, a0);
                s1 += q.y; a1 = fmaf(q.y, f01.y, a1);
                s2 += q.z; a2 = fmaf(q.z, f23.x, a2);
                s3 += q.w; a3 = fmaf(q.w, f23.y, a3);
            }
        } else {
            for (int j = 0; j < cnt; j++) {
                float4 q = wbuf[w][j];
                int sj = sbuf[w][j];
                const __half2* hp = (const __half2*)(g_h1th + sj * 128 + lane * 4);
                float2 f01 = __half22float2(hp[0]);
                float2 f23 = __half22float2(hp[1]);
                s0 += q.x; a0 = fmaf(q.x, f01.x, a0);
                s1 += q.y; a1 = fmaf(q.y, f01.y, a1);
                s2 += q.z; a2 = fmaf(q.z, f23.x, a2);
                s3 += q.w; a3 = fmaf(q.w, f23.y, a3);
            }
        }
        __syncwarp();
    }
    float o;
    o = a0 / s0 + b1[lane];       g_hmid[node * 128 + lane]      = fmaxf(o, 0.f);
    o = a1 / s1 + b1[32 + lane];  g_hmid[node * 128 + 32 + lane] = fmaxf(o, 0.f);
    o = a2 / s2 + b1[64 + lane];  g_hmid[node * 128 + 64 + lane] = fmaxf(o, 0.f);
    o = a3 / s3 + b1[96 + lane];  g_hmid[node * 128 + 96 + lane] = fmaxf(o, 0.f);
}

__global__ __launch_bounds__(256) void agg2_kernel(const float* __restrict__ b2,
                                                   float* __restrict__ out, int n) {
    __shared__ float wbuf[8][32];
    __shared__ int   sbuf[8][32];
    int w = threadIdx.x >> 5, lane = threadIdx.x & 31;
    int node = blockIdx.x * 8 + w;
    if (node >= n) return;
    float ad = g_ad2[node];
    int deg = g_cur[node]; if (deg > SLOTS) deg = SLOTS;
    const int* ep = g_ell + node * SLOTS;
    float s = 0.f, a0 = 0.f, a1 = 0.f;

    for (int base = 0; base < deg; base += 32) {
        int i = base + lane;
        float wv = 0.f; int src = 0;
        if (i < deg) {
            src = ep[i];
            float e = g_as2[src] + ad;
            e = e > 0.f ? e : 0.2f * e;
            wv = __expf(fminf(e, 80.f));
        }
        wbuf[w][lane] = wv;
        sbuf[w][lane] = src;
        __syncwarp();
        int cnt = deg - base; if (cnt > 32) cnt = 32;
        if (cnt == 32) {
            #pragma unroll 4
            for (int j = 0; j < 32; j++) {
                float q = wbuf[w][j];
                int sj = sbuf[w][j];
                float2 v = *(const float2*)(g_h2t + sj * 64 + lane * 2);
                s += q; a0 = fmaf(q, v.x, a0); a1 = fmaf(q, v.y, a1);
            }
        } else {
            for (int j = 0; j < cnt; j++) {
                float q = wbuf[w][j];
                int sj = sbuf[w][j];
                float2 v = *(const float2*)(g_h2t + sj * 64 + lane * 2);
                s += q; a0 = fmaf(q, v.x, a0); a1 = fmaf(q, v.y, a1);
            }
        }
        __syncwarp();
    }
    float r = 1.f / s;
    out[node * 64 + lane]      = a0 * r + b2[lane];
    out[node * 64 + 32 + lane] = a1 * r + b2[32 + lane];
}

// ---------------- launch -----------------------------------------------------
extern "C" void kernel_launch(void* const* d_in, const int* in_sizes, int n_in,
                              void* d_out, int out_size) {
    const float* x    = (const float*)d_in[0];
    const int*   esrc = (const int*)d_in[1];
    const int*   edst = (const int*)d_in[2];
    const float* W1   = (const float*)d_in[3];
    const float* as1w = (const float*)d_in[4];
    const float* ad1w = (const float*)d_in[5];
    const float* b1   = (const float*)d_in[6];
    const float* W2   = (const float*)d_in[7];
    const float* as2w = (const float*)d_in[8];
    const float* ad2w = (const float*)d_in[9];
    const float* b2   = (const float*)d_in[10];
    float* out = (float*)d_out;

    int n = in_sizes[0] / 128;
    int E = in_sizes[1];

    void* p;
    float* hmid;
    cudaGetSymbolAddress(&p, g_hmid); hmid = (float*)p;

    zero_cur_kernel<<<(n + 255) / 256, 256>>>(n);

    int gemmBlocks = (n + 127) / 128;
    int fillBlocks = (E + 1023) / 1024;
    gemm1_fill_kernel<<<gemmBlocks + fillBlocks, 256>>>(x, W1, as1w, ad1w,
                                                        esrc, edst, n, E, gemmBlocks);
    int aggBlocks = (n + 7) / 8;
    agg1_kernel<<<aggBlocks, 256>>>(b1, n);
    gemm2_kernel<<<(n + 127) / 128, 128>>>(hmid, W2, as2w, ad2w, n);
    agg2_kernel<<<aggBlocks, 256>>>(b2, out, n);
}